// round 12
// baseline (speedup 1.0000x reference)
#include <cuda_runtime.h>
#include <cuda_fp16.h>
#include <math.h>
#include <stdint.h>

// Problem constants
#define Bz 32
#define Sz 512
#define Hz 1024
#define Lz 2
#define WD 4
#define Mz (Bz*Sz)        // 16384 rows
#define N2 (2*Hz)         // 2048 proj cols

#define SW128(off) ((off) ^ (((off) >> 3) & 0x70))

__device__ __forceinline__ uint32_t smem_to_u32(const void* p) {
    uint32_t a;
    asm("{ .reg .u64 t; cvta.to.shared.u64 t, %1; cvt.u32.u64 %0, t; }" : "=r"(a) : "l"(p));
    return a;
}

__device__ __forceinline__ void cpasync16(uint32_t dst, const void* src) {
    asm volatile("cp.async.cg.shared.global [%0], [%1], 16;" :: "r"(dst), "l"(src));
}
#define CP_COMMIT() asm volatile("cp.async.commit_group;" ::: "memory")
#define CP_WAIT(n)  asm volatile("cp.async.wait_group %0;" :: "n"(n) : "memory")

__device__ __forceinline__ void ldsm4(uint32_t* r, uint32_t addr) {
    asm volatile("ldmatrix.sync.aligned.m8n8.x4.shared.b16 {%0,%1,%2,%3}, [%4];"
        : "=r"(r[0]), "=r"(r[1]), "=r"(r[2]), "=r"(r[3]) : "r"(addr));
}

__device__ __forceinline__ void mma16816(float* c, const uint32_t* a, const uint32_t* b) {
    asm volatile("mma.sync.aligned.m16n8k16.row.col.f32.f16.f16.f32 "
        "{%0,%1,%2,%3}, {%4,%5,%6,%7}, {%8,%9}, {%0,%1,%2,%3};"
        : "+f"(c[0]), "+f"(c[1]), "+f"(c[2]), "+f"(c[3])
        : "r"(a[0]), "r"(a[1]), "r"(a[2]), "r"(a[3]), "r"(b[0]), "r"(b[1]));
}

// ---------------------------------------------------------------------------
// Scratch (device globals, allocation-free).
// Activation buffers PING-PONGED per highway stage (race-free by construction):
// buf 0 = wsum output (hw0 input), buf 1 = hw0 output (hw1 input).
// ---------------------------------------------------------------------------
__device__ float   g_fo[(size_t)Mz * Hz];
__device__ float   g_bo[(size_t)Mz * Hz];
__device__ float   g_x  [2][2][(size_t)Mz * Hz];
__device__ __half  g_xhi[2][2][(size_t)Mz * Hz];
// Transposed fp16 weights: [widx=8][jblk=16][nn=128][k=1024]
// nn interleave within 64-hidden block: nl at (hp>>3)*16+(hp&7), gate +8.
__device__ __half  g_Whi[(size_t)8 * 2048 * 1024];

// ---------------------------------------------------------------------------
// prep_w: transpose + fp16 round + nl/gate 8-col interleave
// widx = dir*4 + l*2 + hw
// ---------------------------------------------------------------------------
__global__ void prep_w_kernel(const float* __restrict__ fw_W,
                              const float* __restrict__ bw_W) {
    int widx = blockIdx.z;
    const float* W = (widx >= 4 ? bw_W : fw_W) +
                     ((size_t)((widx >> 1) & 1) * 2 + (widx & 1)) * Hz * N2;
    __shared__ float tile[32][33];
    int k0 = blockIdx.y * 32, n0 = blockIdx.x * 32;
    int tx = threadIdx.x, ty = threadIdx.y;
#pragma unroll
    for (int i = 0; i < 4; i++) {
        int ky = ty + 8 * i;
        tile[ky][tx] = W[(size_t)(k0 + ky) * N2 + n0 + tx];
    }
    __syncthreads();
#pragma unroll
    for (int i = 0; i < 4; i++) {
        int ny = ty + 8 * i;
        int n = n0 + ny;
        int h = n & 1023;
        int half = n >> 10;           // 0 = nl, 1 = gate
        int jb = h >> 6;              // 16 column-blocks of 64 hidden
        int hp = h & 63;
        int p = (hp >> 3) * 16 + (hp & 7) + half * 8;   // 0..127
        size_t orow = ((size_t)widx * 2048 + jb * 128 + p) * Hz + k0 + tx;
        g_Whi[orow] = __float2half(tile[tx][ny]);
    }
}

// ---------------------------------------------------------------------------
// window sum -> g_x[dir][0] (float) + g_xhi[dir][0] (fp16)
// blockIdx.y = dir.  At l==0 the stream state IS the inputs array.
// ---------------------------------------------------------------------------
__global__ void wsum_kernel(const float* __restrict__ inputs,
                            const float* __restrict__ pf,
                            const float* __restrict__ pb,
                            const float* __restrict__ fw_w,
                            const float* __restrict__ bw_w, int l) {
    int dir = blockIdx.y;
    const float* o  = (l == 0) ? inputs : (dir ? g_bo : g_fo);
    const float* w5 = dir ? bw_w : fw_w;
    int m  = blockIdx.x;
    int t  = m & (Sz - 1);
    int h4 = threadIdx.x;
    float4 acc = make_float4(0.f, 0.f, 0.f, 0.f);
#pragma unroll
    for (int k = 0; k <= WD; k++) {
        int p = t + k + (dir ? 0 : -WD);
        const float4* src;
        if (p < 0)        src = (const float4*)(pf + (size_t)(p + WD) * Hz);
        else if (p >= Sz) src = (const float4*)(pb + (size_t)(p - Sz) * Hz);
        else              src = (const float4*)(o  + (size_t)(m - t + p) * Hz);
        float wk = w5[k];
        float4 v = src[h4];
        acc.x += wk * v.x; acc.y += wk * v.y;
        acc.z += wk * v.z; acc.w += wk * v.w;
    }
    size_t o4 = (size_t)m * (Hz / 4) + h4;
    ((float4*)g_x[dir][0])[o4] = acc;
    ((__half2*)g_xhi[dir][0])[o4 * 2 + 0] =
        __halves2half2(__float2half(acc.x), __float2half(acc.y));
    ((__half2*)g_xhi[dir][0])[o4 * 2 + 1] =
        __halves2half2(__float2half(acc.z), __float2half(acc.w));
}

// ---------------------------------------------------------------------------
// fp16 mma.sync GEMM (single product) + fused highway epilogue.
// CTA: 128 M x 128 proj (interleaved nl/gate), 256 thr, 8 warps as 2M x 4N,
// warp tile 64x32 (LDSM:MMA = 6:16), BK=64, 3-stage cp.async, 2 CTAs/SM.
// grid (16, 128, 2=dir). hw selects src buffer; hw0 writes buf 1 (ping-pong).
// ---------------------------------------------------------------------------
#define OFF_A   0
#define OFF_B   16384
#define STAGE   32768
#define SMEM_BYTES (3 * STAGE)   // 98304 per CTA -> 2 CTAs/SM

__global__ void __launch_bounds__(256, 2)
gemm_hw_kernel(const float* __restrict__ fw_b, const float* __restrict__ bw_b,
               float* __restrict__ out, int l, int hw) {
    extern __shared__ char sm[];
    uint32_t sb = smem_to_u32(sm);
    int tid = threadIdx.x, wid = tid >> 5, lane = tid & 31;
    int wy = wid & 1, wx = wid >> 1;           // 2 M-warps x 4 N-warps
    int jcta = blockIdx.x;                     // 0..15 (64 hidden cols each)
    int m0 = blockIdx.y * 128;
    int dir = blockIdx.z;
    int widx = dir * 4 + l * 2 + hw;
    const float* bias = (dir ? bw_b : fw_b) + (size_t)l * 2 * N2 + (size_t)hw * N2;
    const __half* xhi = g_xhi[dir][hw];        // src buffer = hw
    const size_t wbase = (size_t)widx * 2048 * 1024 + (size_t)jcta * 128 * 1024;

    float acc[4][4][4];   // [mt 0..3][n8 0..3][frag]
#pragma unroll
    for (int mt = 0; mt < 4; mt++)
#pragma unroll
        for (int j = 0; j < 4; j++)
#pragma unroll
            for (int e = 0; e < 4; e++) acc[mt][j][e] = 0.f;

    // lane-invariant pieces of ldmatrix addresses
    int a_row  = wy * 64 + (lane & 15);                      // + mt*16
    int a_colb = (lane >> 4) * 16;                           // + ks*32
    int b_row  = wx * 32 + ((lane >> 4) << 3) + (lane & 7);  // + jp*16
    int b_colb = ((lane >> 3) & 1) * 16;                     // + ks*32

#define LOAD_STAGE(c, stg) do { \
    int cc = (c); uint32_t so_base = (stg); \
    _Pragma("unroll") \
    for (int i = 0; i < 4; i++) { \
        int idx = tid + 256 * i; int row = idx >> 3, q = idx & 7; \
        uint32_t so = SW128((uint32_t)(row * 128 + q * 16)); \
        cpasync16(sb + so_base + OFF_A + so, \
                  xhi + (size_t)(m0 + row) * Hz + cc * 64 + q * 8); \
        cpasync16(sb + so_base + OFF_B + so, \
                  g_Whi + wbase + (size_t)row * Hz + cc * 64 + q * 8); \
    } \
    CP_COMMIT(); \
} while (0)

    LOAD_STAGE(0, 0);
    LOAD_STAGE(1, STAGE);

    for (int c = 0; c < 16; c++) {
        uint32_t stg = (c % 3) * STAGE;
        if (c + 2 < 16) {
            LOAD_STAGE(c + 2, ((c + 2) % 3) * STAGE);
            CP_WAIT(2);
        } else if (c + 1 < 16) {
            CP_WAIT(1);
        } else {
            CP_WAIT(0);
        }
        __syncthreads();

#pragma unroll
        for (int ks = 0; ks < 4; ks++) {
            uint32_t Ah[4][4];
#pragma unroll
            for (int mt = 0; mt < 4; mt++) {
                uint32_t off = SW128((uint32_t)((a_row + mt * 16) * 128 +
                                                a_colb + ks * 32));
                ldsm4(Ah[mt], sb + stg + OFF_A + off);
            }
            uint32_t Bh[2][4];
#pragma unroll
            for (int jp = 0; jp < 2; jp++) {
                uint32_t off = SW128((uint32_t)((b_row + jp * 16) * 128 +
                                                b_colb + ks * 32));
                ldsm4(Bh[jp], sb + stg + OFF_B + off);
            }
#pragma unroll
            for (int mt = 0; mt < 4; mt++)
#pragma unroll
                for (int jp = 0; jp < 2; jp++) {
                    mma16816(acc[mt][2 * jp],     Ah[mt], Bh[jp] + 0);
                    mma16816(acc[mt][2 * jp + 1], Ah[mt], Bh[jp] + 2);
                }
        }
        __syncthreads();
    }

    // ---- fused highway epilogue (in registers) ----
    // Warp covers rows [m0 + wy*64, +64), proj cols [wx*32, +32) =
    // hidden cols [jcta*64 + wx*16, +16) as 2 (nl,gate) 8-col pairs.
    float* state = dir ? g_bo : g_fo;
    const float* gx_in = g_x[dir][hw];
#pragma unroll
    for (int mt = 0; mt < 4; mt++) {
        int r0 = m0 + wy * 64 + mt * 16 + (lane >> 2);
#pragma unroll
        for (int p = 0; p < 2; p++) {
            int h = jcta * 64 + wx * 16 + p * 8 + (lane & 3) * 2;
            float bn0 = bias[h],        bn1 = bias[h + 1];
            float bg0 = bias[1024 + h], bg1 = bias[1024 + h + 1];
            const float* nlr = acc[mt][2 * p];
            const float* gr  = acc[mt][2 * p + 1];
#pragma unroll
            for (int hf = 0; hf < 2; hf++) {
                int r = r0 + hf * 8;
                size_t gp = (size_t)r * Hz + h;
                float nl0 = nlr[hf * 2 + 0] + bn0;
                float nl1 = nlr[hf * 2 + 1] + bn1;
                float gg0 = gr[hf * 2 + 0] + bg0;
                float gg1 = gr[hf * 2 + 1] + bg1;
                float gs0 = 1.f / (1.f + __expf(-gg0));
                float gs1 = 1.f / (1.f + __expf(-gg1));
                float2 xo = *(const float2*)(gx_in + gp);
                float r0v = gs0 * xo.x + (1.f - gs0) * fmaxf(nl0, 0.f);
                float r1v = gs1 * xo.y + (1.f - gs1) * fmaxf(nl1, 0.f);
                if (hw == 0) {
                    // write NEW x to buffer 1 (ping-pong: no reader races)
                    *(float2*)(g_x[dir][1] + gp) = make_float2(r0v, r1v);
                    ((__half2*)g_xhi[dir][1])[gp / 2] = __halves2half2(
                        __float2half(r0v), __float2half(r1v));
                } else {
                    if (l) {
                        float2 st = *(const float2*)(state + gp);
                        r0v += st.x; r1v += st.y;
                    }
                    *(float2*)(state + gp) = make_float2(r0v, r1v);
                    *(float2*)(out + ((size_t)l * Mz + r) * N2 +
                               (size_t)dir * Hz + h) = make_float2(r0v, r1v);
                }
            }
        }
    }
}

// ---------------------------------------------------------------------------
extern "C" void kernel_launch(void* const* d_in, const int* in_sizes, int n_in,
                              void* d_out, int out_size) {
    const float* inputs = (const float*)d_in[0];
    const float* fw_pad = (const float*)d_in[2];
    const float* bw_pad = (const float*)d_in[3];
    const float* fw_w   = (const float*)d_in[4];
    const float* bw_w   = (const float*)d_in[5];
    const float* fw_W   = (const float*)d_in[6];
    const float* fw_b   = (const float*)d_in[7];
    const float* bw_W   = (const float*)d_in[8];
    const float* bw_b   = (const float*)d_in[9];
    float* out = (float*)d_out;

    cudaFuncSetAttribute(gemm_hw_kernel,
                         cudaFuncAttributeMaxDynamicSharedMemorySize, SMEM_BYTES);

    prep_w_kernel<<<dim3(64, 32, 8), dim3(32, 8)>>>(fw_W, bw_W);

    for (int l = 0; l < Lz; l++) {
        wsum_kernel<<<dim3(Mz, 2), 256>>>(inputs,
                                          fw_pad + (size_t)l * WD * Hz,
                                          bw_pad + (size_t)l * WD * Hz,
                                          fw_w + (size_t)l * (WD + 1),
                                          bw_w + (size_t)l * (WD + 1), l);
        for (int hw = 0; hw < 2; hw++) {
            gemm_hw_kernel<<<dim3(16, 128, 2), 256, SMEM_BYTES>>>(
                fw_b, bw_b, out, l, hw);
        }
    }
}

// round 13
// speedup vs baseline: 1.0412x; 1.0412x over previous
#include <cuda_runtime.h>
#include <cuda_fp16.h>
#include <math.h>
#include <stdint.h>

// Problem constants
#define Bz 32
#define Sz 512
#define Hz 1024
#define Lz 2
#define WD 4
#define Mz (Bz*Sz)        // 16384 rows
#define N2 (2*Hz)         // 2048 proj cols

#define SW128(off) ((off) ^ (((off) >> 3) & 0x70))

__device__ __forceinline__ uint32_t smem_to_u32(const void* p) {
    uint32_t a;
    asm("{ .reg .u64 t; cvta.to.shared.u64 t, %1; cvt.u32.u64 %0, t; }" : "=r"(a) : "l"(p));
    return a;
}

__device__ __forceinline__ void cpasync16(uint32_t dst, const void* src) {
    asm volatile("cp.async.cg.shared.global [%0], [%1], 16;" :: "r"(dst), "l"(src));
}
#define CP_COMMIT() asm volatile("cp.async.commit_group;" ::: "memory")
#define CP_WAIT(n)  asm volatile("cp.async.wait_group %0;" :: "n"(n) : "memory")

__device__ __forceinline__ void ldsm4(uint32_t* r, uint32_t addr) {
    asm volatile("ldmatrix.sync.aligned.m8n8.x4.shared.b16 {%0,%1,%2,%3}, [%4];"
        : "=r"(r[0]), "=r"(r[1]), "=r"(r[2]), "=r"(r[3]) : "r"(addr));
}

__device__ __forceinline__ void mma16816(float* c, const uint32_t* a, const uint32_t* b) {
    asm volatile("mma.sync.aligned.m16n8k16.row.col.f32.f16.f16.f32 "
        "{%0,%1,%2,%3}, {%4,%5,%6,%7}, {%8,%9}, {%0,%1,%2,%3};"
        : "+f"(c[0]), "+f"(c[1]), "+f"(c[2]), "+f"(c[3])
        : "r"(a[0]), "r"(a[1]), "r"(a[2]), "r"(a[3]), "r"(b[0]), "r"(b[1]));
}

// ---------------------------------------------------------------------------
// Scratch (device globals, allocation-free).
// Activation buffers PING-PONGED per highway stage (race-free by construction):
// buf 0 = wsum output (hw0 input), buf 1 = hw0 output (hw1 input).
// ---------------------------------------------------------------------------
__device__ float   g_fo[(size_t)Mz * Hz];
__device__ float   g_bo[(size_t)Mz * Hz];
__device__ float   g_x  [2][2][(size_t)Mz * Hz];
__device__ __half  g_xhi[2][2][(size_t)Mz * Hz];
// Transposed fp16 weights: [widx=8][jblk=16][nn=128][k=1024]
// nn interleave within 64-hidden block: nl at (hp>>3)*16+(hp&7), gate +8.
__device__ __half  g_Whi[(size_t)8 * 2048 * 1024];

// ---------------------------------------------------------------------------
// prep_w: transpose + fp16 round + nl/gate 8-col interleave
// widx = dir*4 + l*2 + hw
// ---------------------------------------------------------------------------
__global__ void prep_w_kernel(const float* __restrict__ fw_W,
                              const float* __restrict__ bw_W) {
    int widx = blockIdx.z;
    const float* W = (widx >= 4 ? bw_W : fw_W) +
                     ((size_t)((widx >> 1) & 1) * 2 + (widx & 1)) * Hz * N2;
    __shared__ float tile[32][33];
    int k0 = blockIdx.y * 32, n0 = blockIdx.x * 32;
    int tx = threadIdx.x, ty = threadIdx.y;
#pragma unroll
    for (int i = 0; i < 4; i++) {
        int ky = ty + 8 * i;
        tile[ky][tx] = W[(size_t)(k0 + ky) * N2 + n0 + tx];
    }
    __syncthreads();
#pragma unroll
    for (int i = 0; i < 4; i++) {
        int ny = ty + 8 * i;
        int n = n0 + ny;
        int h = n & 1023;
        int half = n >> 10;           // 0 = nl, 1 = gate
        int jb = h >> 6;              // 16 column-blocks of 64 hidden
        int hp = h & 63;
        int p = (hp >> 3) * 16 + (hp & 7) + half * 8;   // 0..127
        size_t orow = ((size_t)widx * 2048 + jb * 128 + p) * Hz + k0 + tx;
        g_Whi[orow] = __float2half(tile[tx][ny]);
    }
}

// ---------------------------------------------------------------------------
// window sum -> g_x[dir][0] (float) + g_xhi[dir][0] (fp16)
// blockIdx.y = dir.  At l==0 the stream state IS the inputs array.
// ---------------------------------------------------------------------------
__global__ void wsum_kernel(const float* __restrict__ inputs,
                            const float* __restrict__ pf,
                            const float* __restrict__ pb,
                            const float* __restrict__ fw_w,
                            const float* __restrict__ bw_w, int l) {
    int dir = blockIdx.y;
    const float* o  = (l == 0) ? inputs : (dir ? g_bo : g_fo);
    const float* w5 = dir ? bw_w : fw_w;
    int m  = blockIdx.x;
    int t  = m & (Sz - 1);
    int h4 = threadIdx.x;
    float4 acc = make_float4(0.f, 0.f, 0.f, 0.f);
#pragma unroll
    for (int k = 0; k <= WD; k++) {
        int p = t + k + (dir ? 0 : -WD);
        const float4* src;
        if (p < 0)        src = (const float4*)(pf + (size_t)(p + WD) * Hz);
        else if (p >= Sz) src = (const float4*)(pb + (size_t)(p - Sz) * Hz);
        else              src = (const float4*)(o  + (size_t)(m - t + p) * Hz);
        float wk = w5[k];
        float4 v = src[h4];
        acc.x += wk * v.x; acc.y += wk * v.y;
        acc.z += wk * v.z; acc.w += wk * v.w;
    }
    size_t o4 = (size_t)m * (Hz / 4) + h4;
    ((float4*)g_x[dir][0])[o4] = acc;
    ((__half2*)g_xhi[dir][0])[o4 * 2 + 0] =
        __halves2half2(__float2half(acc.x), __float2half(acc.y));
    ((__half2*)g_xhi[dir][0])[o4 * 2 + 1] =
        __halves2half2(__float2half(acc.z), __float2half(acc.w));
}

// ---------------------------------------------------------------------------
// fp16 mma.sync GEMM (single product) + fused highway epilogue.
// CTA: 128 M x 128 proj (interleaved nl/gate), 256 thr, 8 warps as 2M x 4N,
// warp tile 64x32, BK=64, 3-stage cp.async ring with ONE barrier per k-iter
// (loads issued after compute -> safe with 3 stages), 2 CTAs/SM.
// grid (16, 128, 2=dir). hw selects src buffer; hw0 writes buf 1 (ping-pong).
// ---------------------------------------------------------------------------
#define OFF_A   0
#define OFF_B   16384
#define STAGE   32768
#define SMEM_BYTES (3 * STAGE)   // 98304 per CTA -> 2 CTAs/SM

__global__ void __launch_bounds__(256, 2)
gemm_hw_kernel(const float* __restrict__ fw_b, const float* __restrict__ bw_b,
               float* __restrict__ out, int l, int hw) {
    extern __shared__ char sm[];
    uint32_t sb = smem_to_u32(sm);
    int tid = threadIdx.x, wid = tid >> 5, lane = tid & 31;
    int wy = wid & 1, wx = wid >> 1;           // 2 M-warps x 4 N-warps
    int jcta = blockIdx.x;                     // 0..15 (64 hidden cols each)
    int m0 = blockIdx.y * 128;
    int dir = blockIdx.z;
    int widx = dir * 4 + l * 2 + hw;
    const float* bias = (dir ? bw_b : fw_b) + (size_t)l * 2 * N2 + (size_t)hw * N2;
    const __half* xhi = g_xhi[dir][hw];        // src buffer = hw
    const size_t wbase = (size_t)widx * 2048 * 1024 + (size_t)jcta * 128 * 1024;

    float acc[4][4][4];   // [mt 0..3][n8 0..3][frag]
#pragma unroll
    for (int mt = 0; mt < 4; mt++)
#pragma unroll
        for (int j = 0; j < 4; j++)
#pragma unroll
            for (int e = 0; e < 4; e++) acc[mt][j][e] = 0.f;

    // lane-invariant pieces of ldmatrix addresses
    int a_row  = wy * 64 + (lane & 15);                      // + mt*16
    int a_colb = (lane >> 4) * 16;                           // + ks*32
    int b_row  = wx * 32 + ((lane >> 4) << 3) + (lane & 7);  // + jp*16
    int b_colb = ((lane >> 3) & 1) * 16;                     // + ks*32

    // precomputed per-thread load pointers (advance by 64 halves per stage)
    const __half* aptr[4];
    const __half* bptr[4];
    uint32_t      soff[4];
#pragma unroll
    for (int i = 0; i < 4; i++) {
        int idx = tid + 256 * i, row = idx >> 3, q = idx & 7;
        aptr[i] = xhi + (size_t)(m0 + row) * Hz + q * 8;
        bptr[i] = g_Whi + wbase + (size_t)row * Hz + q * 8;
        soff[i] = SW128((uint32_t)(row * 128 + q * 16));
    }

#define LOAD_STAGE(c, stg) do { \
    uint32_t so_base = (stg); int koff = (c) * 64; \
    _Pragma("unroll") \
    for (int i = 0; i < 4; i++) { \
        cpasync16(sb + so_base + OFF_A + soff[i], aptr[i] + koff); \
        cpasync16(sb + so_base + OFF_B + soff[i], bptr[i] + koff); \
    } \
    CP_COMMIT(); \
} while (0)

    LOAD_STAGE(0, 0);
    LOAD_STAGE(1, STAGE);

    for (int c = 0; c < 16; c++) {
        uint32_t stg = (c % 3) * STAGE;
        if (c + 1 < 16) { CP_WAIT(1); } else { CP_WAIT(0); }
        __syncthreads();   // single barrier per iteration

#pragma unroll
        for (int ks = 0; ks < 4; ks++) {
            uint32_t Ah[4][4];
#pragma unroll
            for (int mt = 0; mt < 4; mt++) {
                uint32_t off = SW128((uint32_t)((a_row + mt * 16) * 128 +
                                                a_colb + ks * 32));
                ldsm4(Ah[mt], sb + stg + OFF_A + off);
            }
            uint32_t Bh[2][4];
#pragma unroll
            for (int jp = 0; jp < 2; jp++) {
                uint32_t off = SW128((uint32_t)((b_row + jp * 16) * 128 +
                                                b_colb + ks * 32));
                ldsm4(Bh[jp], sb + stg + OFF_B + off);
            }
#pragma unroll
            for (int mt = 0; mt < 4; mt++)
#pragma unroll
                for (int jp = 0; jp < 2; jp++) {
                    mma16816(acc[mt][2 * jp],     Ah[mt], Bh[jp] + 0);
                    mma16816(acc[mt][2 * jp + 1], Ah[mt], Bh[jp] + 2);
                }
        }

        // issue next load AFTER compute: targets stage (c+2)%3, which no
        // warp is reading this iteration or next; wraparound to c%3 only
        // happens after all warps pass the next barrier.
        if (c + 2 < 16) LOAD_STAGE(c + 2, ((c + 2) % 3) * STAGE);
    }

    // ---- fused highway epilogue (in registers) ----
    // Warp covers rows [m0 + wy*64, +64), proj cols [wx*32, +32) =
    // hidden cols [jcta*64 + wx*16, +16) as 2 (nl,gate) 8-col pairs.
    float* state = dir ? g_bo : g_fo;
    const float* gx_in = g_x[dir][hw];
#pragma unroll
    for (int mt = 0; mt < 4; mt++) {
        int r0 = m0 + wy * 64 + mt * 16 + (lane >> 2);
#pragma unroll
        for (int p = 0; p < 2; p++) {
            int h = jcta * 64 + wx * 16 + p * 8 + (lane & 3) * 2;
            float bn0 = bias[h],        bn1 = bias[h + 1];
            float bg0 = bias[1024 + h], bg1 = bias[1024 + h + 1];
            const float* nlr = acc[mt][2 * p];
            const float* gr  = acc[mt][2 * p + 1];
#pragma unroll
            for (int hf = 0; hf < 2; hf++) {
                int r = r0 + hf * 8;
                size_t gp = (size_t)r * Hz + h;
                float nl0 = nlr[hf * 2 + 0] + bn0;
                float nl1 = nlr[hf * 2 + 1] + bn1;
                float gg0 = gr[hf * 2 + 0] + bg0;
                float gg1 = gr[hf * 2 + 1] + bg1;
                float gs0 = 1.f / (1.f + __expf(-gg0));
                float gs1 = 1.f / (1.f + __expf(-gg1));
                float2 xo = *(const float2*)(gx_in + gp);
                float r0v = gs0 * xo.x + (1.f - gs0) * fmaxf(nl0, 0.f);
                float r1v = gs1 * xo.y + (1.f - gs1) * fmaxf(nl1, 0.f);
                if (hw == 0) {
                    // write NEW x to buffer 1 (ping-pong: no reader races)
                    *(float2*)(g_x[dir][1] + gp) = make_float2(r0v, r1v);
                    ((__half2*)g_xhi[dir][1])[gp / 2] = __halves2half2(
                        __float2half(r0v), __float2half(r1v));
                } else {
                    if (l) {
                        float2 st = *(const float2*)(state + gp);
                        r0v += st.x; r1v += st.y;
                    }
                    *(float2*)(state + gp) = make_float2(r0v, r1v);
                    *(float2*)(out + ((size_t)l * Mz + r) * N2 +
                               (size_t)dir * Hz + h) = make_float2(r0v, r1v);
                }
            }
        }
    }
}

// ---------------------------------------------------------------------------
extern "C" void kernel_launch(void* const* d_in, const int* in_sizes, int n_in,
                              void* d_out, int out_size) {
    const float* inputs = (const float*)d_in[0];
    const float* fw_pad = (const float*)d_in[2];
    const float* bw_pad = (const float*)d_in[3];
    const float* fw_w   = (const float*)d_in[4];
    const float* bw_w   = (const float*)d_in[5];
    const float* fw_W   = (const float*)d_in[6];
    const float* fw_b   = (const float*)d_in[7];
    const float* bw_W   = (const float*)d_in[8];
    const float* bw_b   = (const float*)d_in[9];
    float* out = (float*)d_out;

    cudaFuncSetAttribute(gemm_hw_kernel,
                         cudaFuncAttributeMaxDynamicSharedMemorySize, SMEM_BYTES);

    prep_w_kernel<<<dim3(64, 32, 8), dim3(32, 8)>>>(fw_W, bw_W);

    for (int l = 0; l < Lz; l++) {
        wsum_kernel<<<dim3(Mz, 2), 256>>>(inputs,
                                          fw_pad + (size_t)l * WD * Hz,
                                          bw_pad + (size_t)l * WD * Hz,
                                          fw_w + (size_t)l * (WD + 1),
                                          bw_w + (size_t)l * (WD + 1), l);
        for (int hw = 0; hw < 2; hw++) {
            gemm_hw_kernel<<<dim3(16, 128, 2), 256, SMEM_BYTES>>>(
                fw_b, bw_b, out, l, hw);
        }
    }
}